// round 15
// baseline (speedup 1.0000x reference)
#include <cuda_runtime.h>
#include <cuda_fp16.h>
#include <cstdint>

#define BATCH 4
#define NB 262144
#define NA 8192
#define FDIM 32
#define HID 64
#define OUT 32

// pair-interleave physical word position within each 8-word block
#define PH(j) (((j) & ~7) | ((((j) & 3) << 1) | ((((j) >> 2)) & 1)))

// bond-kernel smem byte offsets
#define O_W1 0
#define O_W2 6144
#define O_W3 16384
#define O_X  21504
#define O_B2 41984
#define O_B3 42240
#define BOND_SMEM 42368
#define W1SW 24   // words (96B)
#define W2SW 40   // words (160B)
#define W3SW 40
#define XW 40     // fp16 X row stride in words (160B)
#define RS 40     // fp32 restage row stride in words — MUST equal XW (warp-local overlay)

__device__ __align__(16) float g_AP1[BATCH * NA * HID];
__device__ __align__(16) float g_AP2[BATCH * NA * HID];
__device__ __align__(16) float g_accum[BATCH * NA * OUT];
__device__ int   g_count[BATCH * NA];
__device__ float g_bsum[BATCH * OUT];
__device__ float g_asum[BATCH * OUT];
__device__ float g_hb[BATCH * HID];
__device__ __align__(16) unsigned char g_wimg[21504]; // fp16 weight image (pair-interleaved)
__device__ int g_sink;

__device__ __forceinline__ float softplus_f(float x) {
    float e = __expf(-fabsf(x));
    return fmaxf(x, 0.0f) + __logf(1.0f + e);
}
__device__ __forceinline__ uint32_t packh(float a, float b) {
    uint32_t r; asm("cvt.rn.f16x2.f32 %0, %1, %2;" : "=r"(r) : "f"(b), "f"(a)); return r;
}
__device__ __forceinline__ void mma16(float* c, uint32_t a0, uint32_t a1, uint32_t a2, uint32_t a3,
                                      uint32_t b0, uint32_t b1) {
    asm volatile("mma.sync.aligned.m16n8k16.row.col.f32.f16.f16.f32 "
        "{%0,%1,%2,%3}, {%4,%5,%6,%7}, {%8,%9}, {%0,%1,%2,%3};"
        : "+f"(c[0]), "+f"(c[1]), "+f"(c[2]), "+f"(c[3])
        : "r"(a0), "r"(a1), "r"(a2), "r"(a3), "r"(b0), "r"(b1));
}
__device__ __forceinline__ void red4(float* p, float a, float b, float c, float d) {
    asm volatile("red.global.add.v4.f32 [%0], {%1,%2,%3,%4};"
                 :: "l"(p), "f"(a), "f"(b), "f"(c), "f"(d) : "memory");
}

// ---------------- launch 0: hb + fp16 weight image (pair-interleaved) + small zeros ----------------
__global__ void hbprep_kernel(const float* __restrict__ state,
                              const float* __restrict__ ew1,
                              const float* __restrict__ eb1,
                              const float* __restrict__ ew2,
                              const float* __restrict__ ew3) {
    int t = threadIdx.x;   // 256
    {
        int b = t >> 6, j = t & 63;
        float acc = eb1[j];
        for (int i = 0; i < FDIM; ++i)
            acc = fmaf(state[b * FDIM + i], ew1[(96 + i) * HID + j], acc);
        g_hb[b * HID + j] = acc;
    }
    if (t < BATCH * OUT) { g_bsum[t] = 0.0f; g_asum[t] = 0.0f; }
    for (int i = t; i < 64 * 32; i += 256) {     // W1: bond rows 64..95 of e_w1
        int n = i >> 5, k = i & 31;
        *(__half*)(g_wimg + O_W1 + n * 96 + PH(k >> 1) * 4 + (k & 1) * 2)
            = __float2half_rn(ew1[(64 + k) * HID + n]);
    }
    for (int i = t; i < 64 * 64; i += 256) {     // W2
        int n = i >> 6, k = i & 63;
        *(__half*)(g_wimg + O_W2 + n * 160 + PH(k >> 1) * 4 + (k & 1) * 2)
            = __float2half_rn(ew2[k * HID + n]);
    }
    for (int i = t; i < 32 * 64; i += 256) {     // W3
        int n = i >> 6, k = i & 63;
        *(__half*)(g_wimg + O_W3 + n * 160 + PH(k >> 1) * 4 + (k & 1) * 2)
            = __float2half_rn(ew3[k * OUT + n]);
    }
}

// ---------------- launch 1: AP tables + zero accum/count ----------------
__global__ void ap_kernel(const float* __restrict__ atoms,
                          const float* __restrict__ ew1) {
    extern __shared__ float sm[];
    float* sW = sm;
    float* scratch = sm + 64 * HID;
    int tid = threadIdx.x;
    int gt = blockIdx.x * blockDim.x + tid;
    {
        float4 z4 = make_float4(0.f, 0.f, 0.f, 0.f);
        float4* za = (float4*)(g_accum) + gt * 8;
#pragma unroll
        for (int i = 0; i < 8; ++i) za[i] = z4;
        g_count[gt] = 0;
    }
    for (int i = tid; i < 64 * HID; i += blockDim.x) sW[i] = ew1[i];
    __syncthreads();
    int a = gt;
    float* row = scratch + tid * 33;
    const float4* arow = reinterpret_cast<const float4*>(atoms + (size_t)a * FDIM);
#pragma unroll
    for (int k = 0; k < 8; ++k) {
        float4 v = arow[k];
        row[4*k] = v.x; row[4*k+1] = v.y; row[4*k+2] = v.z; row[4*k+3] = v.w;
    }
    for (int half = 0; half < 2; ++half) {
        float acc[HID];
#pragma unroll
        for (int j = 0; j < HID; ++j) acc[j] = 0.0f;
        for (int i = 0; i < 32; ++i) {
            float xv = row[i];
            const float4* wr = reinterpret_cast<const float4*>(sW + (half * 32 + i) * HID);
#pragma unroll
            for (int j4 = 0; j4 < 16; ++j4) {
                float4 wv = wr[j4];
                acc[4*j4]   = fmaf(xv, wv.x, acc[4*j4]);
                acc[4*j4+1] = fmaf(xv, wv.y, acc[4*j4+1]);
                acc[4*j4+2] = fmaf(xv, wv.z, acc[4*j4+2]);
                acc[4*j4+3] = fmaf(xv, wv.w, acc[4*j4+3]);
            }
        }
        float4* o = reinterpret_cast<float4*>((half == 0 ? g_AP1 : g_AP2) + (size_t)a * HID);
#pragma unroll
        for (int j4 = 0; j4 < 16; ++j4)
            o[j4] = make_float4(acc[4*j4], acc[4*j4+1], acc[4*j4+2], acc[4*j4+3]);
    }
}

// ---------------- launch 2: separator (aligns ncu capture window onto bond) ----------------
__global__ void sep_kernel() { if (threadIdx.x == 1234) g_sink = 1; }

// ---------------- bond MLP: mma.sync fp16, LDS.64 fragments ----------------
template<int NT, int NS>
__device__ __forceinline__ void gemm_layer(float (&acc)[2][NT][4], const uint32_t* Xw,
        const uint32_t* Wv, int wsw, const int2* st, int w, int g, int tg) {
#pragma unroll
    for (int s = 0; s < NS; ++s) {
        int ak = st[s].x, bkw = st[s].y;
        uint2 b[NT];
#pragma unroll
        for (int nt = 0; nt < NT; ++nt)
            b[nt] = *(((const uint2*)(Wv + (nt * 8 + g) * wsw + bkw)) + tg);
#pragma unroll
        for (int t = 0; t < 2; ++t) {
            int r1 = w * 32 + t * 16 + g, r2 = r1 + 8;
            uint2 A0 = *(((const uint2*)(Xw + r1 * XW + ak)) + tg);
            uint2 A1 = *(((const uint2*)(Xw + r2 * XW + ak)) + tg);
#pragma unroll
            for (int nt = 0; nt < NT; ++nt)
                mma16(acc[t][nt], A0.x, A1.x, A0.y, A1.y, b[nt].x, b[nt].y);
        }
    }
}

template<int NT, bool HB>
__device__ __forceinline__ void epi_store(float (&acc)[2][NT][4], uint32_t* Xw,
        const float* bias, int w, int g, int tg) {
    __syncwarp();
#pragma unroll
    for (int t = 0; t < 2; ++t)
#pragma unroll
        for (int h = 0; h < 2; ++h) {
            int row = w * 32 + t * 16 + h * 8 + g;
#pragma unroll
            for (int np = 0; np < NT / 2; ++np) {
                uint32_t v[2];
#pragma unroll
                for (int e = 0; e < 2; ++e) {
                    int nt = np * 2 + e;
                    int col = nt * 8 + tg * 2;
                    float v0 = acc[t][nt][h * 2], v1 = acc[t][nt][h * 2 + 1];
                    if (HB) { v0 += bias[col]; v1 += bias[col + 1]; }
                    v[e] = packh(softplus_f(v0), softplus_f(v1));
                }
                *(uint2*)(Xw + row * XW + np * 8 + tg * 2) = make_uint2(v[0], v[1]);
            }
        }
    __syncwarp();
}

__global__ void __launch_bounds__(128, 5) bond_kernel(
        const float* __restrict__ bonds,
        const int* __restrict__ ia1,
        const int* __restrict__ ia2,
        const float* __restrict__ eb2,
        const float* __restrict__ eb3,
        float* __restrict__ out) {
    extern __shared__ __align__(16) unsigned char smem[];
    const int tid = threadIdx.x, lane = tid & 31;
    const int w = tid >> 5, g = lane >> 2, tg = lane & 3;
    const int base = blockIdx.x * 128, batch = base >> 18;
    uint32_t* Xw = (uint32_t*)(smem + O_X);
    float* Xf = (float*)(smem + O_X);
    float* sB2 = (float*)(smem + O_B2);
    float* sB3 = (float*)(smem + O_B3);

    {   // stage fp16 weight image (21504 B, linear)
        const uint4* s = (const uint4*)g_wimg;
        uint4* d = (uint4*)smem;
        for (int i = tid; i < 1344; i += 128) d[i] = s[i];
    }
    if (tid < 64) sB2[tid] = eb2[tid];
    if (tid < 32) sB3[tid] = eb3[tid];

    {   // stage X0 fp16 (row = tid): 16 logical words, pair-interleaved positions
        const float4* br = (const float4*)(bonds + (size_t)(base + tid) * FDIM);
        uint32_t* xr = Xw + tid * XW;
#pragma unroll
        for (int c = 0; c < 8; ++c) {
            float4 v = br[c];
            xr[PH(2 * c)]     = packh(v.x, v.y);
            xr[PH(2 * c + 1)] = packh(v.z, v.w);
        }
    }

    // ---- layer-1 acc init = AP1[a1] + AP2[a2] + hb (exact fp32); overlaps staging ----
    float acc[2][8][4];
    float2 hbv[8];
    {
        const float2* hbp = (const float2*)(g_hb + batch * HID);
#pragma unroll
        for (int nt = 0; nt < 8; ++nt) hbv[nt] = __ldg(hbp + nt * 4 + tg);
    }
#pragma unroll
    for (int t = 0; t < 2; ++t)
#pragma unroll
        for (int h = 0; h < 2; ++h) {
            int row = w * 32 + t * 16 + h * 8 + g;
            int i1 = __ldg(ia1 + base + row), i2 = __ldg(ia2 + base + row);
            const float2* p1 = (const float2*)(g_AP1 + ((size_t)batch * NA + i1) * HID);
            const float2* p2 = (const float2*)(g_AP2 + ((size_t)batch * NA + i2) * HID);
#pragma unroll
            for (int nt = 0; nt < 8; ++nt) {
                float2 u = __ldg(p1 + nt * 4 + tg), vv = __ldg(p2 + nt * 4 + tg);
                acc[t][nt][h * 2]     = u.x + vv.x + hbv[nt].x;
                acc[t][nt][h * 2 + 1] = u.y + vv.y + hbv[nt].y;
            }
        }
    __syncthreads();

    // ---- layer 1 (K=32, 2 steps) ----
    {
        const int2 S1[2] = {{0,0},{8,8}};
        gemm_layer<8, 2>(acc, Xw, (const uint32_t*)(smem + O_W1), W1SW, S1, w, g, tg);
    }
    epi_store<8, false>(acc, Xw, (const float*)0, w, g, tg);

    // ---- layer 2 (K=64, 4 steps) ----
#pragma unroll
    for (int t = 0; t < 2; ++t)
#pragma unroll
        for (int nt = 0; nt < 8; ++nt)
#pragma unroll
            for (int q = 0; q < 4; ++q) acc[t][nt][q] = 0.0f;
    {
        const int2 S2[4] = {{0,0},{8,8},{16,16},{24,24}};
        gemm_layer<8, 4>(acc, Xw, (const uint32_t*)(smem + O_W2), W2SW, S2, w, g, tg);
    }
    epi_store<8, true>(acc, Xw, sB2, w, g, tg);

    // ---- layer 3 (N=32, K=64, 4 steps) ----
    float a3[2][4][4];
#pragma unroll
    for (int t = 0; t < 2; ++t)
#pragma unroll
        for (int nt = 0; nt < 4; ++nt)
#pragma unroll
            for (int q = 0; q < 4; ++q) a3[t][nt][q] = 0.0f;
    {
        const int2 S3[4] = {{0,0},{8,8},{16,16},{24,24}};
        gemm_layer<4, 4>(a3, Xw, (const uint32_t*)(smem + O_W3), W3SW, S3, w, g, tg);
    }

    // ---- final epilogue: softplus -> fp32 restage (warp-local, in-place overlay) ----
    __syncwarp();   // all reads of this warp's fp16 X rows done before overwrite
#pragma unroll
    for (int t = 0; t < 2; ++t)
#pragma unroll
        for (int h = 0; h < 2; ++h) {
            int row = w * 32 + t * 16 + h * 8 + g;
#pragma unroll
            for (int nt = 0; nt < 4; ++nt) {
                int col = nt * 8 + tg * 2;
                float v0 = softplus_f(a3[t][nt][h * 2] + sB3[col]);
                float v1 = softplus_f(a3[t][nt][h * 2 + 1] + sB3[col + 1]);
                *(float2*)(Xf + row * RS + col) = make_float2(v0, v1);
            }
        }
    __syncwarp();
    {
        int cg = lane & 3;              // column group: cols cg*8 .. cg*8+7
        int rsub = lane >> 2;           // row-subindex 0..7
        float cs[8];
#pragma unroll
        for (int i = 0; i < 8; ++i) cs[i] = 0.0f;
#pragma unroll
        for (int it = 0; it < 4; ++it) {
            int row = w * 32 + it * 8 + rsub;
            float4 q0 = *(float4*)(Xf + row * RS + cg * 8);
            float4 q1 = *(float4*)(Xf + row * RS + cg * 8 + 4);
            int ai = __ldg(ia1 + base + row);
            float* op = out + (size_t)(base + row) * OUT + cg * 8;
            *(float4*)op = q0;
            *(float4*)(op + 4) = q1;
            float* ap = g_accum + ((size_t)batch * NA + ai) * OUT + cg * 8;
            red4(ap, q0.x, q0.y, q0.z, q0.w);
            red4(ap + 4, q1.x, q1.y, q1.z, q1.w);
            if (cg == 0) atomicAdd(&g_count[batch * NA + ai], 1);
            cs[0] += q0.x; cs[1] += q0.y; cs[2] += q0.z; cs[3] += q0.w;
            cs[4] += q1.x; cs[5] += q1.y; cs[6] += q1.z; cs[7] += q1.w;
        }
#pragma unroll
        for (int i = 0; i < 8; ++i) {
            cs[i] += __shfl_xor_sync(0xffffffffu, cs[i], 16);
            cs[i] += __shfl_xor_sync(0xffffffffu, cs[i], 8);
            cs[i] += __shfl_xor_sync(0xffffffffu, cs[i], 4);
        }
        if (lane < 4) {
            float* bp = g_bsum + batch * OUT + lane * 8;
            red4(bp, cs[0], cs[1], cs[2], cs[3]);
            red4(bp + 4, cs[4], cs[5], cs[6], cs[7]);
        }
    }
}

// ---------------- atom MLP (scalar; ~3% of work) ----------------
__global__ void atom_kernel(const float* __restrict__ atoms,
                            const float* __restrict__ state,
                            const float* __restrict__ vw1, const float* __restrict__ vb1,
                            const float* __restrict__ vw2, const float* __restrict__ vb2,
                            const float* __restrict__ vw3, const float* __restrict__ vb3,
                            float* __restrict__ out) {
    extern __shared__ float sm[];
    float* sW1 = sm;
    float* sW2 = sW1 + 96 * HID;
    float* sW3 = sW2 + HID * HID;
    float* scratch = sW3 + HID * OUT;
    float* sB1 = scratch + 128 * 97;
    float* sB2 = sB1 + HID;
    float* sB3 = sB2 + HID;
    float* sMsum = sB3 + OUT;

    int tid = threadIdx.x;
    int a = blockIdx.x * 128 + tid;
    int b = a >> 13;

    for (int i = tid; i < 96 * HID; i += 128) sW1[i] = vw1[i];
    for (int i = tid; i < HID * HID; i += 128) sW2[i] = vw2[i];
    for (int i = tid; i < HID * OUT; i += 128) sW3[i] = vw3[i];
    if (tid < HID) { sB1[tid] = vb1[tid]; sB2[tid] = vb2[tid]; }
    if (tid < OUT) { sB3[tid] = vb3[tid]; sMsum[tid] = 0.0f; }
    __syncthreads();

    float* row = scratch + tid * 97;
    float inv = 1.0f / (float)g_count[a];
    const float4* pa = reinterpret_cast<const float4*>(g_accum + (size_t)a * OUT);
#pragma unroll
    for (int k = 0; k < 8; ++k) {
        float4 v = pa[k];
        row[4*k] = v.x*inv; row[4*k+1] = v.y*inv; row[4*k+2] = v.z*inv; row[4*k+3] = v.w*inv;
    }
    const float4* pt = reinterpret_cast<const float4*>(atoms + (size_t)a * FDIM);
#pragma unroll
    for (int k = 0; k < 8; ++k) {
        float4 v = pt[k];
        row[32+4*k] = v.x; row[32+4*k+1] = v.y; row[32+4*k+2] = v.z; row[32+4*k+3] = v.w;
    }
    const float4* ps = reinterpret_cast<const float4*>(state + (size_t)b * FDIM);
#pragma unroll
    for (int k = 0; k < 8; ++k) {
        float4 v = ps[k];
        row[64+4*k] = v.x; row[64+4*k+1] = v.y; row[64+4*k+2] = v.z; row[64+4*k+3] = v.w;
    }

    float h[HID];
#pragma unroll
    for (int j = 0; j < HID; ++j) h[j] = sB1[j];
    for (int i = 0; i < 96; ++i) {
        float xv = row[i];
        const float4* wr = reinterpret_cast<const float4*>(sW1 + i * HID);
#pragma unroll
        for (int j4 = 0; j4 < 16; ++j4) {
            float4 wv = wr[j4];
            h[4*j4]   = fmaf(xv, wv.x, h[4*j4]);
            h[4*j4+1] = fmaf(xv, wv.y, h[4*j4+1]);
            h[4*j4+2] = fmaf(xv, wv.z, h[4*j4+2]);
            h[4*j4+3] = fmaf(xv, wv.w, h[4*j4+3]);
        }
    }
#pragma unroll
    for (int j = 0; j < HID; ++j) row[j] = softplus_f(h[j]);

    float h2[HID];
#pragma unroll
    for (int j = 0; j < HID; ++j) h2[j] = sB2[j];
    for (int i = 0; i < HID; ++i) {
        float xv = row[i];
        const float4* wr = reinterpret_cast<const float4*>(sW2 + i * HID);
#pragma unroll
        for (int j4 = 0; j4 < 16; ++j4) {
            float4 wv = wr[j4];
            h2[4*j4]   = fmaf(xv, wv.x, h2[4*j4]);
            h2[4*j4+1] = fmaf(xv, wv.y, h2[4*j4+1]);
            h2[4*j4+2] = fmaf(xv, wv.z, h2[4*j4+2]);
            h2[4*j4+3] = fmaf(xv, wv.w, h2[4*j4+3]);
        }
    }
#pragma unroll
    for (int j = 0; j < HID; ++j) row[j] = softplus_f(h2[j]);

    float h3[OUT];
#pragma unroll
    for (int j = 0; j < OUT; ++j) h3[j] = sB3[j];
    for (int i = 0; i < HID; ++i) {
        float xv = row[i];
        const float4* wr = reinterpret_cast<const float4*>(sW3 + i * OUT);
#pragma unroll
        for (int j4 = 0; j4 < 8; ++j4) {
            float4 wv = wr[j4];
            h3[4*j4]   = fmaf(xv, wv.x, h3[4*j4]);
            h3[4*j4+1] = fmaf(xv, wv.y, h3[4*j4+1]);
            h3[4*j4+2] = fmaf(xv, wv.z, h3[4*j4+2]);
            h3[4*j4+3] = fmaf(xv, wv.w, h3[4*j4+3]);
        }
    }
    float o[OUT];
#pragma unroll
    for (int j = 0; j < OUT; ++j) o[j] = softplus_f(h3[j]);

    float4* orow = reinterpret_cast<float4*>(out + (size_t)(BATCH * NB * OUT) + (size_t)a * OUT);
#pragma unroll
    for (int j4 = 0; j4 < 8; ++j4)
        orow[j4] = make_float4(o[4*j4], o[4*j4+1], o[4*j4+2], o[4*j4+3]);

    int lane = tid & 31;
#pragma unroll
    for (int j = 0; j < OUT; ++j) {
        float v = o[j];
        v += __shfl_xor_sync(0xffffffffu, v, 16);
        v += __shfl_xor_sync(0xffffffffu, v, 8);
        v += __shfl_xor_sync(0xffffffffu, v, 4);
        v += __shfl_xor_sync(0xffffffffu, v, 2);
        v += __shfl_xor_sync(0xffffffffu, v, 1);
        if (lane == 0) atomicAdd(&sMsum[j], v);
    }
    __syncthreads();
    if (tid < OUT) atomicAdd(&g_asum[b * OUT + tid], sMsum[tid]);
}

__global__ void state_kernel(const float* __restrict__ state,
                             const float* __restrict__ uw1, const float* __restrict__ ub1,
                             const float* __restrict__ uw2, const float* __restrict__ ub2,
                             const float* __restrict__ uw3, const float* __restrict__ ub3,
                             float* __restrict__ out) {
    __shared__ float uin[96];
    __shared__ float h1s[HID];
    __shared__ float h2s[HID];
    int b = blockIdx.x;
    int j = threadIdx.x;
    if (j < 32) {
        uin[j] = g_bsum[b * OUT + j] * (1.0f / (float)NB);
        uin[32 + j] = g_asum[b * OUT + j] * (1.0f / (float)NA);
        uin[64 + j] = state[b * FDIM + j];
    }
    __syncthreads();
    float acc = ub1[j];
    for (int i = 0; i < 96; ++i) acc = fmaf(uin[i], uw1[i * HID + j], acc);
    h1s[j] = softplus_f(acc);
    __syncthreads();
    acc = ub2[j];
    for (int i = 0; i < HID; ++i) acc = fmaf(h1s[i], uw2[i * HID + j], acc);
    h2s[j] = softplus_f(acc);
    __syncthreads();
    if (j < OUT) {
        acc = ub3[j];
        for (int i = 0; i < HID; ++i) acc = fmaf(h2s[i], uw3[i * OUT + j], acc);
        out[(size_t)(BATCH * NB * OUT) + (size_t)(BATCH * NA * OUT) + b * OUT + j] = softplus_f(acc);
    }
}

extern "C" void kernel_launch(void* const* d_in, const int* in_sizes, int n_in,
                              void* d_out, int out_size) {
    const float* bonds = (const float*)d_in[0];
    const int* ia1 = (const int*)d_in[1];
    const int* ia2 = (const int*)d_in[2];
    const float* atoms = (const float*)d_in[3];
    const float* state = (const float*)d_in[4];
    const float* ew1 = (const float*)d_in[5];
    const float* eb1 = (const float*)d_in[6];
    const float* ew2 = (const float*)d_in[7];
    const float* eb2 = (const float*)d_in[8];
    const float* ew3 = (const float*)d_in[9];
    const float* eb3 = (const float*)d_in[10];
    const float* vw1 = (const float*)d_in[11];
    const float* vb1 = (const float*)d_in[12];
    const float* vw2 = (const float*)d_in[13];
    const float* vb2 = (const float*)d_in[14];
    const float* vw3 = (const float*)d_in[15];
    const float* vb3 = (const float*)d_in[16];
    const float* uw1 = (const float*)d_in[17];
    const float* ub1 = (const float*)d_in[18];
    const float* uw2 = (const float*)d_in[19];
    const float* ub2 = (const float*)d_in[20];
    const float* uw3 = (const float*)d_in[21];
    const float* ub3 = (const float*)d_in[22];
    float* out = (float*)d_out;

    const int AP_SMEM   = (64 * HID + 128 * 33) * (int)sizeof(float);
    const int ATOM_SMEM = (96 * HID + HID * HID + HID * OUT + 128 * 97
                           + HID + HID + OUT + OUT) * (int)sizeof(float);

    cudaFuncSetAttribute(ap_kernel, cudaFuncAttributeMaxDynamicSharedMemorySize, AP_SMEM);
    cudaFuncSetAttribute(bond_kernel, cudaFuncAttributeMaxDynamicSharedMemorySize, BOND_SMEM);
    cudaFuncSetAttribute(atom_kernel, cudaFuncAttributeMaxDynamicSharedMemorySize, ATOM_SMEM);

    hbprep_kernel<<<1, 256>>>(state, ew1, eb1, ew2, ew3);                 // 0
    ap_kernel<<<(BATCH * NA) / 128, 128, AP_SMEM>>>(atoms, ew1);          // 1
    sep_kernel<<<1, 32>>>();                                              // 2
    bond_kernel<<<(BATCH * NB) / 128, 128, BOND_SMEM>>>(bonds, ia1, ia2, eb2, eb3, out);  // 3 (ncu target)
    atom_kernel<<<(BATCH * NA) / 128, 128, ATOM_SMEM>>>(atoms, state, vw1, vb1, vw2, vb2, vw3, vb3, out);
    state_kernel<<<BATCH, 64>>>(state, uw1, ub1, uw2, ub2, uw3, ub3, out);
}

// round 16
// speedup vs baseline: 1.0273x; 1.0273x over previous
#include <cuda_runtime.h>
#include <cuda_fp16.h>
#include <cstdint>

#define BATCH 4
#define NB 262144
#define NA 8192
#define FDIM 32
#define HID 64
#define OUT 32

// bond-kernel smem byte offsets (R12 layout)
#define O_W1 0
#define O_W2 5120
#define O_W3 14336
#define O_X  18944
#define O_B2 37376
#define O_B3 37632
#define BOND_SMEM 37888
#define W1SW 20   // W1 row stride in words (80B)
#define W2SW 36   // 144B
#define W3SW 36
#define XW 36     // fp16 X row stride in words (144B)
#define RS 36     // fp32 restage row stride in words (144B) == XW (warp-local overlay)

__device__ __align__(16) float g_AP1[BATCH * NA * HID];
__device__ __align__(16) float g_AP2[BATCH * NA * HID];
__device__ __align__(16) float g_accum[BATCH * NA * OUT];
__device__ int   g_count[BATCH * NA];
__device__ float g_bsum[BATCH * OUT];
__device__ float g_asum[BATCH * OUT];
__device__ float g_hb[BATCH * HID];
__device__ __align__(16) unsigned char g_wimg[19200]; // fp16 weight image
__device__ int g_sink;

__device__ __forceinline__ float softplus_f(float x) {
    float e = __expf(-fabsf(x));
    return fmaxf(x, 0.0f) + __logf(1.0f + e);
}
__device__ __forceinline__ uint32_t packh(float a, float b) {
    uint32_t r; asm("cvt.rn.f16x2.f32 %0, %1, %2;" : "=r"(r) : "f"(b), "f"(a)); return r;
}
__device__ __forceinline__ void mma16(float* c, uint32_t a0, uint32_t a1, uint32_t a2, uint32_t a3,
                                      uint32_t b0, uint32_t b1) {
    asm volatile("mma.sync.aligned.m16n8k16.row.col.f32.f16.f16.f32 "
        "{%0,%1,%2,%3}, {%4,%5,%6,%7}, {%8,%9}, {%0,%1,%2,%3};"
        : "+f"(c[0]), "+f"(c[1]), "+f"(c[2]), "+f"(c[3])
        : "r"(a0), "r"(a1), "r"(a2), "r"(a3), "r"(b0), "r"(b1));
}
__device__ __forceinline__ void red4(float* p, float a, float b, float c, float d) {
    asm volatile("red.global.add.v4.f32 [%0], {%1,%2,%3,%4};"
                 :: "l"(p), "f"(a), "f"(b), "f"(c), "f"(d) : "memory");
}

// ---------------- launch 0: hb + fp16 weight image + small zeros ----------------
__global__ void hbprep_kernel(const float* __restrict__ state,
                              const float* __restrict__ ew1,
                              const float* __restrict__ eb1,
                              const float* __restrict__ ew2,
                              const float* __restrict__ ew3) {
    int t = threadIdx.x;   // 256
    {
        int b = t >> 6, j = t & 63;
        float acc = eb1[j];
        for (int i = 0; i < FDIM; ++i)
            acc = fmaf(state[b * FDIM + i], ew1[(96 + i) * HID + j], acc);
        g_hb[b * HID + j] = acc;
    }
    if (t < BATCH * OUT) { g_bsum[t] = 0.0f; g_asum[t] = 0.0f; }
    for (int i = t; i < 64 * 32; i += 256) {     // W1: bond rows 64..95 of e_w1
        int n = i >> 5, k = i & 31;
        *(__half*)(g_wimg + O_W1 + n * 80 + k * 2) = __float2half_rn(ew1[(64 + k) * HID + n]);
    }
    for (int i = t; i < 64 * 64; i += 256) {     // W2
        int n = i >> 6, k = i & 63;
        *(__half*)(g_wimg + O_W2 + n * 144 + k * 2) = __float2half_rn(ew2[k * HID + n]);
    }
    for (int i = t; i < 32 * 64; i += 256) {     // W3
        int n = i >> 6, k = i & 63;
        *(__half*)(g_wimg + O_W3 + n * 144 + k * 2) = __float2half_rn(ew3[k * OUT + n]);
    }
}

// ---------------- launch 1: AP tables + zero accum/count ----------------
__global__ void ap_kernel(const float* __restrict__ atoms,
                          const float* __restrict__ ew1) {
    extern __shared__ float sm[];
    float* sW = sm;
    float* scratch = sm + 64 * HID;
    int tid = threadIdx.x;
    int gt = blockIdx.x * blockDim.x + tid;
    {
        float4 z4 = make_float4(0.f, 0.f, 0.f, 0.f);
        float4* za = (float4*)(g_accum) + gt * 8;
#pragma unroll
        for (int i = 0; i < 8; ++i) za[i] = z4;
        g_count[gt] = 0;
    }
    for (int i = tid; i < 64 * HID; i += blockDim.x) sW[i] = ew1[i];
    __syncthreads();
    int a = gt;
    float* row = scratch + tid * 33;
    const float4* arow = reinterpret_cast<const float4*>(atoms + (size_t)a * FDIM);
#pragma unroll
    for (int k = 0; k < 8; ++k) {
        float4 v = arow[k];
        row[4*k] = v.x; row[4*k+1] = v.y; row[4*k+2] = v.z; row[4*k+3] = v.w;
    }
    for (int half = 0; half < 2; ++half) {
        float acc[HID];
#pragma unroll
        for (int j = 0; j < HID; ++j) acc[j] = 0.0f;
        for (int i = 0; i < 32; ++i) {
            float xv = row[i];
            const float4* wr = reinterpret_cast<const float4*>(sW + (half * 32 + i) * HID);
#pragma unroll
            for (int j4 = 0; j4 < 16; ++j4) {
                float4 wv = wr[j4];
                acc[4*j4]   = fmaf(xv, wv.x, acc[4*j4]);
                acc[4*j4+1] = fmaf(xv, wv.y, acc[4*j4+1]);
                acc[4*j4+2] = fmaf(xv, wv.z, acc[4*j4+2]);
                acc[4*j4+3] = fmaf(xv, wv.w, acc[4*j4+3]);
            }
        }
        float4* o = reinterpret_cast<float4*>((half == 0 ? g_AP1 : g_AP2) + (size_t)a * HID);
#pragma unroll
        for (int j4 = 0; j4 < 16; ++j4)
            o[j4] = make_float4(acc[4*j4], acc[4*j4+1], acc[4*j4+2], acc[4*j4+3]);
    }
}

// ---------------- launch 2: separator (aligns ncu capture window onto bond) ----------------
__global__ void sep_kernel() { if (threadIdx.x == 1234) g_sink = 1; }

// ---------------- bond MLP: mma.sync fp16 single-pass GEMM, 2 tiles per CTA ----------------
template<int NT, int NS>
__device__ __forceinline__ void gemm_layer(float (&acc)[2][NT][4], const uint32_t* Xw,
        const uint32_t* Wv, int wsw, const int2* st, int w, int g, int tg) {
#pragma unroll
    for (int s = 0; s < NS; ++s) {
        int ak = st[s].x, bkw = st[s].y;
        uint32_t b0[NT], b1[NT];
#pragma unroll
        for (int nt = 0; nt < NT; ++nt) {
            const uint32_t* bp = Wv + (nt * 8 + g) * wsw + bkw + tg;
            b0[nt] = bp[0]; b1[nt] = bp[4];
        }
#pragma unroll
        for (int t = 0; t < 2; ++t) {
            int r1 = w * 32 + t * 16 + g, r2 = r1 + 8;
            int i1 = r1 * XW + ((r1 >> 3) & 3) + ak + tg;
            int i2 = r2 * XW + ((r2 >> 3) & 3) + ak + tg;
            uint32_t a0 = Xw[i1], a2 = Xw[i1 + 4], a1 = Xw[i2], a3 = Xw[i2 + 4];
#pragma unroll
            for (int nt = 0; nt < NT; ++nt) mma16(acc[t][nt], a0, a1, a2, a3, b0[nt], b1[nt]);
        }
    }
}

template<int NT, bool HB>
__device__ __forceinline__ void epi_store(float (&acc)[2][NT][4], uint32_t* Xw,
        const float* bias, int w, int g, int tg) {
    __syncwarp();
#pragma unroll
    for (int t = 0; t < 2; ++t)
#pragma unroll
        for (int h = 0; h < 2; ++h) {
            int row = w * 32 + t * 16 + h * 8 + g;
            int rw = row * XW + ((row >> 3) & 3);
#pragma unroll
            for (int nt = 0; nt < NT; ++nt) {
                int col = nt * 8 + tg * 2;
                float v0 = acc[t][nt][h * 2], v1 = acc[t][nt][h * 2 + 1];
                if (HB) { v0 += bias[col]; v1 += bias[col + 1]; }
                v0 = softplus_f(v0); v1 = softplus_f(v1);
                Xw[rw + (col >> 1)] = packh(v0, v1);
            }
        }
    __syncwarp();
}

__global__ void __launch_bounds__(128, 5) bond_kernel(
        const float* __restrict__ bonds,
        const int* __restrict__ ia1,
        const int* __restrict__ ia2,
        const float* __restrict__ eb2,
        const float* __restrict__ eb3,
        float* __restrict__ out) {
    extern __shared__ __align__(16) unsigned char smem[];
    const int tid = threadIdx.x, lane = tid & 31;
    const int w = tid >> 5, g = lane >> 2, tg = lane & 3;
    const int cbase = blockIdx.x * 256, batch = cbase >> 18;
    uint32_t* Xw = (uint32_t*)(smem + O_X);
    float* Xf = (float*)(smem + O_X);
    float* sB2 = (float*)(smem + O_B2);
    float* sB3 = (float*)(smem + O_B3);

    {   // stage fp16 weight image once (18944 B, linear)
        const uint4* s = (const uint4*)g_wimg;
        uint4* d = (uint4*)smem;
        for (int i = tid; i < 1184; i += 128) d[i] = s[i];
    }
    if (tid < 64) sB2[tid] = eb2[tid];
    if (tid < 32) sB3[tid] = eb3[tid];

    // hoist hb to registers once per CTA
    float2 hbv[8];
    {
        const float2* hbp = (const float2*)(g_hb + batch * HID);
#pragma unroll
        for (int nt = 0; nt < 8; ++nt) hbv[nt] = __ldg(hbp + nt * 4 + tg);
    }
    __syncthreads();

    for (int tile = 0; tile < 2; ++tile) {
        const int base = cbase + tile * 128;

        {   // stage X0 fp16 (row = tid, warp-local): 16 words
            const float4* br = (const float4*)(bonds + (size_t)(base + tid) * FDIM);
            int rw = tid * XW + ((tid >> 3) & 3);
#pragma unroll
            for (int c = 0; c < 8; ++c) {
                float4 v = br[c];
                Xw[rw + c * 2]     = packh(v.x, v.y);
                Xw[rw + c * 2 + 1] = packh(v.z, v.w);
            }
        }

        // layer-1 acc init = AP1[a1] + AP2[a2] + hb (exact fp32); gathers overlap staging
        float acc[2][8][4];
#pragma unroll
        for (int t = 0; t < 2; ++t)
#pragma unroll
            for (int h = 0; h < 2; ++h) {
                int row = w * 32 + t * 16 + h * 8 + g;
                int i1 = __ldg(ia1 + base + row), i2 = __ldg(ia2 + base + row);
                const float2* p1 = (const float2*)(g_AP1 + ((size_t)batch * NA + i1) * HID);
                const float2* p2 = (const float2*)(g_AP2 + ((size_t)batch * NA + i2) * HID);
#pragma unroll
                for (int nt = 0; nt < 8; ++nt) {
                    float2 u = __ldg(p1 + nt * 4 + tg), vv = __ldg(p2 + nt * 4 + tg);
                    acc[t][nt][h * 2]     = u.x + vv.x + hbv[nt].x;
                    acc[t][nt][h * 2 + 1] = u.y + vv.y + hbv[nt].y;
                }
            }
        __syncwarp();   // X staging is warp-local

        // ---- layer 1 (K=32, 2 steps) ----
        {
            const int2 S1[2] = {{0,0},{8,8}};
            gemm_layer<8, 2>(acc, Xw, (const uint32_t*)(smem + O_W1), W1SW, S1, w, g, tg);
        }
        epi_store<8, false>(acc, Xw, (const float*)0, w, g, tg);

        // ---- layer 2 (K=64, 4 steps) ----
#pragma unroll
        for (int t = 0; t < 2; ++t)
#pragma unroll
            for (int nt = 0; nt < 8; ++nt)
#pragma unroll
                for (int q = 0; q < 4; ++q) acc[t][nt][q] = 0.0f;
        {
            const int2 S2[4] = {{0,0},{8,8},{16,16},{24,24}};
            gemm_layer<8, 4>(acc, Xw, (const uint32_t*)(smem + O_W2), W2SW, S2, w, g, tg);
        }
        epi_store<8, true>(acc, Xw, sB2, w, g, tg);

        // ---- layer 3 (N=32, K=64, 4 steps) ----
        float a3[2][4][4];
#pragma unroll
        for (int t = 0; t < 2; ++t)
#pragma unroll
            for (int nt = 0; nt < 4; ++nt)
#pragma unroll
                for (int q = 0; q < 4; ++q) a3[t][nt][q] = 0.0f;
        {
            const int2 S3[4] = {{0,0},{8,8},{16,16},{24,24}};
            gemm_layer<4, 4>(a3, Xw, (const uint32_t*)(smem + O_W3), W3SW, S3, w, g, tg);
        }

        // ---- final epilogue: softplus -> fp32 restage (warp-local overlay) -> STG + red.v4 ----
        __syncwarp();
#pragma unroll
        for (int t = 0; t < 2; ++t)
#pragma unroll
            for (int h = 0; h < 2; ++h) {
                int row = w * 32 + t * 16 + h * 8 + g;
#pragma unroll
                for (int nt = 0; nt < 4; ++nt) {
                    int col = nt * 8 + tg * 2;
                    float v0 = softplus_f(a3[t][nt][h * 2] + sB3[col]);
                    float v1 = softplus_f(a3[t][nt][h * 2 + 1] + sB3[col + 1]);
                    *(float2*)(Xf + row * RS + col) = make_float2(v0, v1);
                }
            }
        __syncwarp();
        {
            int cg = lane & 3;              // column group: cols cg*8 .. cg*8+7
            int rsub = lane >> 2;           // row-subindex 0..7
            float cs[8];
#pragma unroll
            for (int i = 0; i < 8; ++i) cs[i] = 0.0f;
#pragma unroll
            for (int it = 0; it < 4; ++it) {
                int row = w * 32 + it * 8 + rsub;
                float4 q0 = *(float4*)(Xf + row * RS + cg * 8);
                float4 q1 = *(float4*)(Xf + row * RS + cg * 8 + 4);
                int ai = __ldg(ia1 + base + row);
                float* op = out + (size_t)(base + row) * OUT + cg * 8;
                *(float4*)op = q0;
                *(float4*)(op + 4) = q1;
                float* ap = g_accum + ((size_t)batch * NA + ai) * OUT + cg * 8;
                red4(ap, q0.x, q0.y, q0.z, q0.w);
                red4(ap + 4, q1.x, q1.y, q1.z, q1.w);
                if (cg == 0) atomicAdd(&g_count[batch * NA + ai], 1);
                cs[0] += q0.x; cs[1] += q0.y; cs[2] += q0.z; cs[3] += q0.w;
                cs[4] += q1.x; cs[5] += q1.y; cs[6] += q1.z; cs[7] += q1.w;
            }
#pragma unroll
            for (int i = 0; i < 8; ++i) {
                cs[i] += __shfl_xor_sync(0xffffffffu, cs[i], 16);
                cs[i] += __shfl_xor_sync(0xffffffffu, cs[i], 8);
                cs[i] += __shfl_xor_sync(0xffffffffu, cs[i], 4);
            }
            if (lane < 4) {
                float* bp = g_bsum + batch * OUT + lane * 8;
                red4(bp, cs[0], cs[1], cs[2], cs[3]);
                red4(bp + 4, cs[4], cs[5], cs[6], cs[7]);
            }
        }
        __syncwarp();   // restage reads done before next tile overwrites X
    }
}

// ---------------- atom MLP (scalar; ~3% of work) ----------------
__global__ void atom_kernel(const float* __restrict__ atoms,
                            const float* __restrict__ state,
                            const float* __restrict__ vw1, const float* __restrict__ vb1,
                            const float* __restrict__ vw2, const float* __restrict__ vb2,
                            const float* __restrict__ vw3, const float* __restrict__ vb3,
                            float* __restrict__ out) {
    extern __shared__ float sm[];
    float* sW1 = sm;
    float* sW2 = sW1 + 96 * HID;
    float* sW3 = sW2 + HID * HID;
    float* scratch = sW3 + HID * OUT;
    float* sB1 = scratch + 128 * 97;
    float* sB2 = sB1 + HID;
    float* sB3 = sB2 + HID;
    float* sMsum = sB3 + OUT;

    int tid = threadIdx.x;
    int a = blockIdx.x * 128 + tid;
    int b = a >> 13;

    for (int i = tid; i < 96 * HID; i += 128) sW1[i] = vw1[i];
    for (int i = tid; i < HID * HID; i += 128) sW2[i] = vw2[i];
    for (int i = tid; i < HID * OUT; i += 128) sW3[i] = vw3[i];
    if (tid < HID) { sB1[tid] = vb1[tid]; sB2[tid] = vb2[tid]; }
    if (tid < OUT) { sB3[tid] = vb3[tid]; sMsum[tid] = 0.0f; }
    __syncthreads();

    float* row = scratch + tid * 97;
    float inv = 1.0f / (float)g_count[a];
    const float4* pa = reinterpret_cast<const float4*>(g_accum + (size_t)a * OUT);
#pragma unroll
    for (int k = 0; k < 8; ++k) {
        float4 v = pa[k];
        row[4*k] = v.x*inv; row[4*k+1] = v.y*inv; row[4*k+2] = v.z*inv; row[4*k+3] = v.w*inv;
    }
    const float4* pt = reinterpret_cast<const float4*>(atoms + (size_t)a * FDIM);
#pragma unroll
    for (int k = 0; k < 8; ++k) {
        float4 v = pt[k];
        row[32+4*k] = v.x; row[32+4*k+1] = v.y; row[32+4*k+2] = v.z; row[32+4*k+3] = v.w;
    }
    const float4* ps = reinterpret_cast<const float4*>(state + (size_t)b * FDIM);
#pragma unroll
    for (int k = 0; k < 8; ++k) {
        float4 v = ps[k];
        row[64+4*k] = v.x; row[64+4*k+1] = v.y; row[64+4*k+2] = v.z; row[64+4*k+3] = v.w;
    }

    float h[HID];
#pragma unroll
    for (int j = 0; j < HID; ++j) h[j] = sB1[j];
    for (int i = 0; i < 96; ++i) {
        float xv = row[i];
        const float4* wr = reinterpret_cast<const float4*>(sW1 + i * HID);
#pragma unroll
        for (int j4 = 0; j4 < 16; ++j4) {
            float4 wv = wr[j4];
            h[4*j4]   = fmaf(xv, wv.x, h[4*j4]);
            h[4*j4+1] = fmaf(xv, wv.y, h[4*j4+1]);
            h[4*j4+2] = fmaf(xv, wv.z, h[4*j4+2]);
            h[4*j4+3] = fmaf(xv, wv.w, h[4*j4+3]);
        }
    }
#pragma unroll
    for (int j = 0; j < HID; ++j) row[j] = softplus_f(h[j]);

    float h2[HID];
#pragma unroll
    for (int j = 0; j < HID; ++j) h2[j] = sB2[j];
    for (int i = 0; i < HID; ++i) {
        float xv = row[i];
        const float4* wr = reinterpret_cast<const float4*>(sW2 + i * HID);
#pragma unroll
        for (int j4 = 0; j4 < 16; ++j4) {
            float4 wv = wr[j4];
            h2[4*j4]   = fmaf(xv, wv.x, h2[4*j4]);
            h2[4*j4+1] = fmaf(xv, wv.y, h2[4*j4+1]);
            h2[4*j4+2] = fmaf(xv, wv.z, h2[4*j4+2]);
            h2[4*j4+3] = fmaf(xv, wv.w, h2[4*j4+3]);
        }
    }
#pragma unroll
    for (int j = 0; j < HID; ++j) row[j] = softplus_f(h2[j]);

    float h3[OUT];
#pragma unroll
    for (int j = 0; j < OUT; ++j) h3[j] = sB3[j];
    for (int i = 0; i < HID; ++i) {
        float xv = row[i];
        const float4* wr = reinterpret_cast<const float4*>(sW3 + i * OUT);
#pragma unroll
        for (int j4 = 0; j4 < 8; ++j4) {
            float4 wv = wr[j4];
            h3[4*j4]   = fmaf(xv, wv.x, h3[4*j4]);
            h3[4*j4+1] = fmaf(xv, wv.y, h3[4*j4+1]);
            h3[4*j4+2] = fmaf(xv, wv.z, h3[4*j4+2]);
            h3[4*j4+3] = fmaf(xv, wv.w, h3[4*j4+3]);
        }
    }
    float o[OUT];
#pragma unroll
    for (int j = 0; j < OUT; ++j) o[j] = softplus_f(h3[j]);

    float4* orow = reinterpret_cast<float4*>(out + (size_t)(BATCH * NB * OUT) + (size_t)a * OUT);
#pragma unroll
    for (int j4 = 0; j4 < 8; ++j4)
        orow[j4] = make_float4(o[4*j4], o[4*j4+1], o[4*j4+2], o[4*j4+3]);

    int lane = tid & 31;
#pragma unroll
    for (int j = 0; j < OUT; ++j) {
        float v = o[j];
        v += __shfl_xor_sync(0xffffffffu, v, 16);
        v += __shfl_xor_sync(0xffffffffu, v, 8);
        v += __shfl_xor_sync(0xffffffffu, v, 4);
        v += __shfl_xor_sync(0xffffffffu, v, 2);
        v += __shfl_xor_sync(0xffffffffu, v, 1);
        if (lane == 0) atomicAdd(&sMsum[j], v);
    }
    __syncthreads();
    if (tid < OUT) atomicAdd(&g_asum[b * OUT + tid], sMsum[tid]);
}

__global__ void state_kernel(const float* __restrict__ state,
                             const float* __restrict__ uw1, const float* __restrict__ ub1,
                             const float* __restrict__ uw2, const float* __restrict__ ub2,
                             const float* __restrict__ uw3, const float* __restrict__ ub3,
                             float* __restrict__ out) {
    __shared__ float uin[96];
    __shared__ float h1s[HID];
    __shared__ float h2s[HID];
    int b = blockIdx.x;
    int j = threadIdx.x;
    if (j < 32) {
        uin[j] = g_bsum[b * OUT + j] * (1.0f / (float)NB);
        uin[32 + j] = g_asum[b * OUT + j] * (1.0f / (float)NA);
        uin[64 + j] = state[b * FDIM + j];
    }
    __syncthreads();
    float acc = ub1[j];
    for (int i = 0; i < 96; ++i) acc = fmaf(uin[i], uw1[i * HID + j], acc);
    h1s[j] = softplus_f(acc);
    __syncthreads();
    acc = ub2[j];
    for (int i = 0; i < HID; ++i) acc = fmaf(h1s[i], uw2[i * HID + j], acc);
    h2s[j] = softplus_f(acc);
    __syncthreads();
    if (j < OUT) {
        acc = ub3[j];
        for (int i = 0; i < HID; ++i) acc = fmaf(h2s[i], uw3[i * OUT + j], acc);
        out[(size_t)(BATCH * NB * OUT) + (size_t)(BATCH * NA * OUT) + b * OUT + j] = softplus_f(acc);
    }
}

extern "C" void kernel_launch(void* const* d_in, const int* in_sizes, int n_in,
                              void* d_out, int out_size) {
    const float* bonds = (const float*)d_in[0];
    const int* ia1 = (const int*)d_in[1];
    const int* ia2 = (const int*)d_in[2];
    const float* atoms = (const float*)d_in[3];
    const float* state = (const float*)d_in[4];
    const float* ew1 = (const float*)d_in[5];
    const float* eb1 = (const float*)d_in[6];
    const float* ew2 = (const float*)d_in[7];
    const float* eb2 = (const float*)d_in[8];
    const float* ew3 = (const float*)d_in[9];
    const float* eb3 = (const float*)d_in[10];
    const float* vw1 = (const float*)d_in[11];
    const float* vb1 = (const float*)d_in[12];
    const float* vw2 = (const float*)d_in[13];
    const float* vb2 = (const float*)d_in[14];
    const float* vw3 = (const float*)d_in[15];
    const float* vb3 = (const float*)d_in[16];
    const float* uw1 = (const float*)d_in[17];
    const float* ub1 = (const float*)d_in[18];
    const float* uw2 = (const float*)d_in[19];
    const float* ub2 = (const float*)d_in[20];
    const float* uw3 = (const float*)d_in[21];
    const float* ub3 = (const float*)d_in[22];
    float* out = (float*)d_out;

    const int AP_SMEM   = (64 * HID + 128 * 33) * (int)sizeof(float);
    const int ATOM_SMEM = (96 * HID + HID * HID + HID * OUT + 128 * 97
                           + HID + HID + OUT + OUT) * (int)sizeof(float);

    cudaFuncSetAttribute(ap_kernel, cudaFuncAttributeMaxDynamicSharedMemorySize, AP_SMEM);
    cudaFuncSetAttribute(bond_kernel, cudaFuncAttributeMaxDynamicSharedMemorySize, BOND_SMEM);
    cudaFuncSetAttribute(atom_kernel, cudaFuncAttributeMaxDynamicSharedMemorySize, ATOM_SMEM);

    hbprep_kernel<<<1, 256>>>(state, ew1, eb1, ew2, ew3);                 // 0
    ap_kernel<<<(BATCH * NA) / 128, 128, AP_SMEM>>>(atoms, ew1);          // 1
    sep_kernel<<<1, 32>>>();                                              // 2
    bond_kernel<<<(BATCH * NB) / 256, 128, BOND_SMEM>>>(bonds, ia1, ia2, eb2, eb3, out);  // 3 (ncu target)
    atom_kernel<<<(BATCH * NA) / 128, 128, ATOM_SMEM>>>(atoms, state, vw1, vb1, vw2, vb2, vw3, vb3, out);
    state_kernel<<<BATCH, 64>>>(state, uw1, ub1, uw2, ub2, uw3, ub3, out);
}